// round 7
// baseline (speedup 1.0000x reference)
#include <cuda_runtime.h>
#include <cuda_bf16.h>
#include <math.h>

// Problem constants
#define DMODEL 256
#define TLEN   64
#define NHEADS 8
#define DHEAD  32
#define SEQS   1024                 // B*H*W
#define TOKENS (SEQS * TLEN)        // 65536
#define OUT_ELEMS  ((long)TOKENS * DMODEL)             // 16,777,216
#define ATTN_ELEMS ((long)SEQS * NHEADS * TLEN * TLEN) // 33,554,432

// GEMM tiling
#define BM 128
#define BN 128
#define BK 16
#define TM 8
#define TN 8

// Scratch (device globals — no allocation allowed)
__device__ __align__(128) float g_q[TOKENS * DMODEL];    // head-split [seq][n][t][dh]
__device__ __align__(128) float g_k[TOKENS * DMODEL];
__device__ __align__(128) float g_v[TOKENS * DMODEL];
__device__ __align__(128) float g_ctx[TOKENS * DMODEL];  // merged heads [token][d]

// ---------------------------------------------------------------------------
// Packed f32x2 helpers (sm_103a: fma.rn.f32x2 = 2 fp32 FMAs per instruction)
// ---------------------------------------------------------------------------
__device__ __forceinline__ unsigned long long pack_dup(float x) {
    unsigned long long r;
    asm("mov.b64 %0, {%1, %2};" : "=l"(r) : "f"(x), "f"(x));
    return r;
}
__device__ __forceinline__ unsigned long long fma2(unsigned long long a,
                                                   unsigned long long b,
                                                   unsigned long long c) {
    unsigned long long d;
    asm("fma.rn.f32x2 %0, %1, %2, %3;" : "=l"(d) : "l"(a), "l"(b), "l"(c));
    return d;
}
__device__ __forceinline__ float2 unpack2(unsigned long long v) {
    float lo, hi;
    asm("mov.b64 {%0, %1}, %2;" : "=f"(lo), "=f"(hi) : "l"(v));
    return make_float2(lo, hi);
}

// ---------------------------------------------------------------------------
// Tiled fp32 GEMM (f32x2 inner loop): C[M x 256] = A[M x 256] @ W[256 x 256] + b
// MODE 0: plain row-major store.  MODE 1: head-split store for q/k/v.
// grid: (256/BN, M/BM) ; block: 256 threads ; each thread 8x8 microtile.
// ---------------------------------------------------------------------------
template <int MODE>
__device__ __forceinline__ void gemm_body(const float* __restrict__ A,
                                          const float* __restrict__ W,
                                          const float* __restrict__ bias,
                                          float* __restrict__ C)
{
    __shared__ __align__(16) float  Ast[BK][BM + 4];   // transposed A tile [k][m]
    __shared__ __align__(16) float4 Bs[BK][BN / 4];    // B tile [k][n4]

    const int tid = threadIdx.x;
    const int m0  = blockIdx.y * BM;
    const int n0  = blockIdx.x * BN;
    const int ty  = tid >> 4;   // 0..15
    const int tx  = tid & 15;   // 0..15

    // 8x8 accumulator as 8x4 packed f32x2 (cols 2j, 2j+1)
    unsigned long long acc2[TM][TN / 2];
#pragma unroll
    for (int i = 0; i < TM; i++)
#pragma unroll
        for (int j = 0; j < TN / 2; j++) acc2[i][j] = 0ull;

    for (int k0 = 0; k0 < DMODEL; k0 += BK) {
        // Load A tile: 128x16 floats = 512 float4, 2 per thread (transpose into smem)
#pragma unroll
        for (int i = 0; i < 2; i++) {
            int idx = tid + i * 256;           // [0,512)
            int row = idx >> 2;                // [0,128)
            int c4  = idx & 3;                 // [0,4)
            float4 a = *(const float4*)&A[(size_t)(m0 + row) * DMODEL + k0 + c4 * 4];
            Ast[c4 * 4 + 0][row] = a.x;
            Ast[c4 * 4 + 1][row] = a.y;
            Ast[c4 * 4 + 2][row] = a.z;
            Ast[c4 * 4 + 3][row] = a.w;
        }
        // Load B tile: 16x128 floats = 512 float4
#pragma unroll
        for (int i = 0; i < 2; i++) {
            int idx = tid + i * 256;           // [0,512)
            int row = idx >> 5;                // [0,16)
            int c4  = idx & 31;                // [0,32)
            Bs[row][c4] = *(const float4*)&W[(size_t)(k0 + row) * DMODEL + n0 + c4 * 4];
        }
        __syncthreads();

#pragma unroll
        for (int k = 0; k < BK; k++) {
            float4 a0 = *(const float4*)&Ast[k][ty * 8];
            float4 a1 = *(const float4*)&Ast[k][ty * 8 + 4];
            float a[TM] = {a0.x, a0.y, a0.z, a0.w, a1.x, a1.y, a1.z, a1.w};
            // 8 B values = 4 packed f32x2 pairs, read directly (16B-aligned smem)
            const unsigned long long* bp =
                (const unsigned long long*)&Bs[k][tx * 2];
            unsigned long long b2[4] = {bp[0], bp[1], bp[2], bp[3]};
#pragma unroll
            for (int i = 0; i < TM; i++) {
                unsigned long long aa = pack_dup(a[i]);
#pragma unroll
                for (int j = 0; j < TN / 2; j++)
                    acc2[i][j] = fma2(aa, b2[j], acc2[i][j]);
            }
        }
        __syncthreads();
    }

    // Unpack accumulators + bias
    float acc[TM][TN];
#pragma unroll
    for (int i = 0; i < TM; i++)
#pragma unroll
        for (int j = 0; j < TN / 2; j++) {
            float2 f = unpack2(acc2[i][j]);
            acc[i][2 * j + 0] = f.x;
            acc[i][2 * j + 1] = f.y;
        }
    float bj[TN];
#pragma unroll
    for (int j = 0; j < TN; j++) bj[j] = bias[n0 + tx * 8 + j];

    if (MODE == 0) {
#pragma unroll
        for (int i = 0; i < TM; i++) {
            int m = m0 + ty * 8 + i;
            float4 w0 = make_float4(acc[i][0] + bj[0], acc[i][1] + bj[1],
                                    acc[i][2] + bj[2], acc[i][3] + bj[3]);
            float4 w1 = make_float4(acc[i][4] + bj[4], acc[i][5] + bj[5],
                                    acc[i][6] + bj[6], acc[i][7] + bj[7]);
            *(float4*)&C[(size_t)m * DMODEL + n0 + tx * 8]     = w0;
            *(float4*)&C[(size_t)m * DMODEL + n0 + tx * 8 + 4] = w1;
        }
    } else {
        // head-split: out[((seq*NH + n)*TLEN + t)*DHEAD + dh]
        int d  = n0 + tx * 8;
        int n  = d >> 5;       // head index
        int dh = d & 31;       // offset within head (multiple of 8)
#pragma unroll
        for (int i = 0; i < TM; i++) {
            int m   = m0 + ty * 8 + i;
            int t   = m & 63;
            int seq = m >> 6;
            size_t base = (((size_t)seq * NHEADS + n) * TLEN + t) * DHEAD + dh;
            float4 w0 = make_float4(acc[i][0] + bj[0], acc[i][1] + bj[1],
                                    acc[i][2] + bj[2], acc[i][3] + bj[3]);
            float4 w1 = make_float4(acc[i][4] + bj[4], acc[i][5] + bj[5],
                                    acc[i][6] + bj[6], acc[i][7] + bj[7]);
            *(float4*)&C[base]     = w0;
            *(float4*)&C[base + 4] = w1;
        }
    }
}

__global__ void __launch_bounds__(256, 2)
qkv_gemm_kernel(const float* __restrict__ q, const float* __restrict__ k,
                const float* __restrict__ v,
                const float* __restrict__ wq, const float* __restrict__ bq,
                const float* __restrict__ wk, const float* __restrict__ bk,
                const float* __restrict__ wv, const float* __restrict__ bv)
{
    int z = blockIdx.z;
    const float *A, *W, *b;
    float* C;
    if (z == 0)      { A = q; W = wq; b = bq; C = g_q; }
    else if (z == 1) { A = k; W = wk; b = bk; C = g_k; }
    else             { A = v; W = wv; b = bv; C = g_v; }
    gemm_body<1>(A, W, b, C);
}

__global__ void __launch_bounds__(256, 2)
out_gemm_kernel(const float* __restrict__ W, const float* __restrict__ b,
                float* __restrict__ C)
{
    if (C == nullptr) C = g_q;  // out not requested: dump to scratch
    gemm_body<0>(g_ctx, W, b, C);
}

// ---------------------------------------------------------------------------
// Attention: one CTA per (seq, head). q,k,v tiles are [64 x 32] fp32.
// logits = (q*scale) @ k^T (f32x2, register-resident) ; parallel softmax
// across the 4 threads of each row via shfl ; ctx = attn @ v
// ---------------------------------------------------------------------------
__global__ void __launch_bounds__(256)
attn_kernel(const float* __restrict__ mask, float* __restrict__ attn_out)
{
    __shared__ float qs[64][33];                       // padded row reads
    __shared__ __align__(16) float kst[32][66];        // k^T [d][t_k]; 66 keeps 8B pair align
    __shared__ __align__(16) float vs[64][32];
    __shared__ __align__(16) float ls[64][68];         // probs; 68 keeps 16B align
    __shared__ float msk[64];

    const int head = blockIdx.x;           // seq*NH + n
    const int b    = head >> 11;           // batch index (seq>>8)
    const int tid  = threadIdx.x;
    const float scale = 0.17677669529663687f;  // 1/sqrt(32)

    const float* qp = g_q + (size_t)head * (TLEN * DHEAD);
    const float* kp = g_k + (size_t)head * (TLEN * DHEAD);
    const float* vp = g_v + (size_t)head * (TLEN * DHEAD);

    if (tid < 64) msk[tid] = mask[b * 64 + tid] * (-1e9f);

    // Load q (pre-scaled), k (transposed), v : 512 float4 each
#pragma unroll
    for (int i = 0; i < 2; i++) {
        int idx = tid + i * 256;           // [0,512)
        int r = idx >> 3;                  // row [0,64)
        int c = (idx & 7) * 4;             // col {0,4,...,28}
        float4 qv = ((const float4*)qp)[idx];
        qs[r][c + 0] = qv.x * scale; qs[r][c + 1] = qv.y * scale;
        qs[r][c + 2] = qv.z * scale; qs[r][c + 3] = qv.w * scale;
        float4 kv = ((const float4*)kp)[idx];
        kst[c + 0][r] = kv.x; kst[c + 1][r] = kv.y;
        kst[c + 2][r] = kv.z; kst[c + 3][r] = kv.w;
        *(float4*)&vs[r][c] = ((const float4*)vp)[idx];
    }
    __syncthreads();

    // Logits + softmax, register-resident.
    // Thread (r = tid>>2, cq = tid&3) owns the 16 contiguous columns
    // c = cq*16 .. cq*16+15 of row r. Quad (lanes 4r..4r+3) covers the row.
    {
        const int r   = tid >> 2;
        const int cq  = tid & 3;
        const int c0  = cq * 16;

        float qr[32];
#pragma unroll
        for (int d = 0; d < 32; d++) qr[d] = qs[r][d];

        // QK^T with packed f32x2: 8 column-pairs per thread
        unsigned long long acc2[8];
#pragma unroll
        for (int p = 0; p < 8; p++) acc2[p] = 0ull;
#pragma unroll
        for (int d = 0; d < 32; d++) {
            unsigned long long aa = pack_dup(qr[d]);
            const unsigned long long* kp2 =
                (const unsigned long long*)&kst[d][c0];   // 8B-aligned (c0 even, row 264B)
#pragma unroll
            for (int p = 0; p < 8; p++)
                acc2[p] = fma2(aa, kp2[p], acc2[p]);
        }

        float lg[16];
#pragma unroll
        for (int p = 0; p < 8; p++) {
            float2 f = unpack2(acc2[p]);
            lg[2 * p + 0] = f.x + msk[c0 + 2 * p + 0];
            lg[2 * p + 1] = f.y + msk[c0 + 2 * p + 1];
        }

        // Row max across 16 local + quad shfl
        float mx = lg[0];
#pragma unroll
        for (int i = 1; i < 16; i++) mx = fmaxf(mx, lg[i]);
        mx = fmaxf(mx, __shfl_xor_sync(0xffffffffu, mx, 1));
        mx = fmaxf(mx, __shfl_xor_sync(0xffffffffu, mx, 2));

        // exp + row sum
        float sum = 0.0f;
#pragma unroll
        for (int i = 0; i < 16; i++) {
            float e = expf(lg[i] - mx);
            lg[i] = e;
            sum += e;
        }
        sum += __shfl_xor_sync(0xffffffffu, sum, 1);
        sum += __shfl_xor_sync(0xffffffffu, sum, 2);
        float inv = 1.0f / sum;

        // Normalize and publish to smem for AV / attn output
#pragma unroll
        for (int p = 0; p < 4; p++) {
            float4 w = make_float4(lg[4 * p + 0] * inv, lg[4 * p + 1] * inv,
                                   lg[4 * p + 2] * inv, lg[4 * p + 3] * inv);
            *(float4*)&ls[r][c0 + 4 * p] = w;
        }
    }
    __syncthreads();

    // Optional attn output write (coalesced)
    if (attn_out != nullptr) {
        float* ap = attn_out + (size_t)head * (TLEN * TLEN);
        for (int i = tid; i < TLEN * TLEN; i += 256)
            ap[i] = ls[i >> 6][i & 63];
    }

    // ctx = attn @ v : thread (r = tid/4) computes dh = (tid&3)*8 .. +7
    {
        int r   = tid >> 2;
        int dh0 = (tid & 3) * 8;
        // 8-wide output as 4 packed f32x2 pairs
        unsigned long long o2[4] = {0ull, 0ull, 0ull, 0ull};
#pragma unroll
        for (int s = 0; s < 64; s++) {
            unsigned long long aa = pack_dup(ls[r][s]);
            const unsigned long long* vp2 =
                (const unsigned long long*)&vs[s][dh0];   // 8B-aligned (row 128B, dh0 mult of 8)
#pragma unroll
            for (int p = 0; p < 4; p++)
                o2[p] = fma2(aa, vp2[p], o2[p]);
        }
        float o[8];
#pragma unroll
        for (int p = 0; p < 4; p++) {
            float2 f = unpack2(o2[p]);
            o[2 * p + 0] = f.x;
            o[2 * p + 1] = f.y;
        }
        int seq = head >> 3;
        int n   = head & 7;
        size_t base = (((size_t)seq * TLEN + r) * DMODEL) + n * DHEAD + dh0;
        *(float4*)&g_ctx[base]     = make_float4(o[0], o[1], o[2], o[3]);
        *(float4*)&g_ctx[base + 4] = make_float4(o[4], o[5], o[6], o[7]);
    }
}

// ---------------------------------------------------------------------------
extern "C" void kernel_launch(void* const* d_in, const int* in_sizes, int n_in,
                              void* d_out, int out_size)
{
    const float* v    = (const float*)d_in[0];
    const float* k    = (const float*)d_in[1];
    const float* q    = (const float*)d_in[2];
    const float* mask = (const float*)d_in[3];
    const float* wq_w = (const float*)d_in[4];
    const float* wq_b = (const float*)d_in[5];
    const float* wk_w = (const float*)d_in[6];
    const float* wk_b = (const float*)d_in[7];
    const float* wv_w = (const float*)d_in[8];
    const float* wv_b = (const float*)d_in[9];
    const float* wo_w = (const float*)d_in[10];
    const float* wo_b = (const float*)d_in[11];

    float* outp  = nullptr;
    float* attnp = nullptr;
    long osz = (long)out_size;
    if (osz >= OUT_ELEMS + ATTN_ELEMS) {      // (out, attn) concatenated
        outp  = (float*)d_out;
        attnp = (float*)d_out + OUT_ELEMS;
    } else if (osz == ATTN_ELEMS) {           // attn only
        attnp = (float*)d_out;
        outp  = nullptr;                      // out goes to scratch inside kernel
    } else {                                  // out only
        outp  = (float*)d_out;
        attnp = nullptr;
    }

    // 1) Fused QKV projections -> head-split scratch
    dim3 g1(DMODEL / BN, TOKENS / BM, 3);
    qkv_gemm_kernel<<<g1, 256>>>(q, k, v, wq_w, wq_b, wk_w, wk_b, wv_w, wv_b);

    // 2) Attention per (seq, head)
    attn_kernel<<<SEQS * NHEADS, 256>>>(mask, attnp);

    // 3) Output projection
    dim3 g2(DMODEL / BN, TOKENS / BM);
    out_gemm_kernel<<<g2, 256>>>(wo_w, wo_b, outp);
}

// round 11
// speedup vs baseline: 1.6102x; 1.6102x over previous
#include <cuda_runtime.h>
#include <cuda_bf16.h>
#include <math.h>

// Problem constants
#define DMODEL 256
#define TLEN   64
#define NHEADS 8
#define DHEAD  32
#define SEQS   1024                 // B*H*W
#define TOKENS (SEQS * TLEN)        // 65536
#define OUT_ELEMS  ((long)TOKENS * DMODEL)             // 16,777,216
#define ATTN_ELEMS ((long)SEQS * NHEADS * TLEN * TLEN) // 33,554,432

// ---------------------------------------------------------------------------
// Device scratch (no allocation allowed)
// ---------------------------------------------------------------------------
__device__ __align__(128) float g_q[TOKENS * DMODEL];    // head-split [seq][n][t][dh]
__device__ __align__(128) float g_k[TOKENS * DMODEL];
__device__ __align__(128) float g_v[TOKENS * DMODEL];
__device__ __align__(128) float g_ctx[TOKENS * DMODEL];  // merged heads [token][d]
// Pre-transposed, hi/lo-split weights: [g][n*256 + k] (bf16 bits as ushort)
__device__ __align__(128) unsigned short g_wt_hi[4][DMODEL * DMODEL];
__device__ __align__(128) unsigned short g_wt_lo[4][DMODEL * DMODEL];

// ---------------------------------------------------------------------------
// Helpers (all baseline sm_80/90 PTX — no 'a'-suffix features)
// ---------------------------------------------------------------------------
__device__ __forceinline__ unsigned smem_u32(const void* p) {
    unsigned a;
    asm("{ .reg .u64 t; cvta.to.shared.u64 t, %1; cvt.u32.u64 %0, t; }"
        : "=r"(a) : "l"(p));
    return a;
}
// pack two fp32 -> bf16x2 (e0 -> low half)
__device__ __forceinline__ unsigned pack_bf2(float e0, float e1) {
    unsigned r;
    asm("cvt.rn.bf16x2.f32 %0, %1, %2;" : "=r"(r) : "f"(e1), "f"(e0));
    return r;
}
__device__ __forceinline__ float bf_round(float x) {
    return __bfloat162float(__float2bfloat16_rn(x));
}
__device__ __forceinline__ void ldmx4(unsigned* r, unsigned addr) {
    asm volatile("ldmatrix.sync.aligned.m8n8.x4.shared.b16 {%0,%1,%2,%3}, [%4];"
                 : "=r"(r[0]), "=r"(r[1]), "=r"(r[2]), "=r"(r[3]) : "r"(addr));
}
__device__ __forceinline__ void mma16816(float* d, const unsigned* a, const unsigned* b) {
    asm volatile(
        "mma.sync.aligned.m16n8k16.row.col.f32.bf16.bf16.f32 "
        "{%0,%1,%2,%3}, {%4,%5,%6,%7}, {%8,%9}, {%0,%1,%2,%3};"
        : "+f"(d[0]), "+f"(d[1]), "+f"(d[2]), "+f"(d[3])
        : "r"(a[0]), "r"(a[1]), "r"(a[2]), "r"(a[3]), "r"(b[0]), "r"(b[1]));
}

// Packed f32x2 helpers (attention kernel — validated passing in R7)
__device__ __forceinline__ unsigned long long pack_dup(float x) {
    unsigned long long r;
    asm("mov.b64 %0, {%1, %2};" : "=l"(r) : "f"(x), "f"(x));
    return r;
}
__device__ __forceinline__ unsigned long long fma2(unsigned long long a,
                                                   unsigned long long b,
                                                   unsigned long long c) {
    unsigned long long d;
    asm("fma.rn.f32x2 %0, %1, %2, %3;" : "=l"(d) : "l"(a), "l"(b), "l"(c));
    return d;
}
__device__ __forceinline__ float2 unpack2(unsigned long long v) {
    float lo, hi;
    asm("mov.b64 {%0, %1}, %2;" : "=f"(lo), "=f"(hi) : "l"(v));
    return make_float2(lo, hi);
}

// ---------------------------------------------------------------------------
// Weight prep: W[k][n] fp32 -> Wt_hi/Wt_lo[n][k] bf16 (transposed + hi/lo split)
// ---------------------------------------------------------------------------
__global__ void prep_weights_kernel(const float* __restrict__ wq,
                                    const float* __restrict__ wk,
                                    const float* __restrict__ wv,
                                    const float* __restrict__ wo)
{
    int i = blockIdx.x * 256 + threadIdx.x;      // 0 .. 4*65536-1
    int g = i >> 16;
    int r = i & 65535;
    int n = r >> 8;
    int k = r & 255;
    const float* W = (g == 0) ? wq : (g == 1) ? wk : (g == 2) ? wv : wo;
    float x = W[k * DMODEL + n];
    __nv_bfloat16 hb = __float2bfloat16_rn(x);
    float hf = __bfloat162float(hb);
    __nv_bfloat16 lb = __float2bfloat16_rn(x - hf);
    g_wt_hi[g][(n << 8) | k] = __bfloat16_as_ushort(hb);
    g_wt_lo[g][(n << 8) | k] = __bfloat16_as_ushort(lb);
}

// ---------------------------------------------------------------------------
// mma.sync bf16 GEMM with hi/lo split:
//   C[65536 x 256] = A[65536 x 256] @ W_g[256 x 256] + bias
// CTA tile 128x128, 8 warps of 64x32. K chunked by 32 (two k16 steps).
// D += Ah*Bh + Al*Bh + Ah*Bl.
// smem rows padded to 40 bf16 = 80B = 5 x 16B units (5 coprime 8 =>
// conflict-free ldmatrix across 8-row groups).
// MODE 0: plain row-major store.  MODE 1: head-split store for q/k/v.
// ---------------------------------------------------------------------------
#define SROW 40

template <int MODE>
__device__ __forceinline__ void gemm_mma(const float* __restrict__ A, int g,
                                         const float* __restrict__ bias,
                                         float* __restrict__ C)
{
    __shared__ __align__(16) unsigned short Ah[128 * SROW];
    __shared__ __align__(16) unsigned short Al[128 * SROW];
    __shared__ __align__(16) unsigned short Bh[128 * SROW];
    __shared__ __align__(16) unsigned short Bl[128 * SROW];
    __shared__ float sbias[DMODEL];

    const int tid  = threadIdx.x;
    const int lane = tid & 31;
    const int wid  = tid >> 5;
    const int m0   = blockIdx.y * 128;
    const int n0   = blockIdx.x * 128;
    const int warp_m = (wid >> 2) * 64;   // 0 or 64
    const int warp_n = (wid & 3) * 32;    // 0,32,64,96

    const unsigned short* __restrict__ WH = g_wt_hi[g];
    const unsigned short* __restrict__ WL = g_wt_lo[g];

    sbias[tid] = bias[tid];

    const unsigned ahB = smem_u32(Ah);
    const unsigned alB = smem_u32(Al);
    const unsigned bhB = smem_u32(Bh);
    const unsigned blB = smem_u32(Bl);

    // ldmatrix lane-address components
    const int lg = lane >> 3;            // address group 0..3
    const int lr = lane & 7;
    // A x4 tile (16 rows x 16 cols): groups = [r0-7,k0-7][r8-15,k0-7][r0-7,k8-15][r8-15,k8-15]
    const int aRow = lr + (lg & 1) * 8;
    const int aKb  = (lg >> 1) * 16;     // byte offset within kstep
    // B x4 covering two 8n-tiles x 16k: groups = [n0-7,k0-7][n0-7,k8-15][n8-15,k0-7][n8-15,k8-15]
    const int bRow = lr + (lg >> 1) * 8;
    const int bKb  = (lg & 1) * 16;

    float acc[4][4][4];
#pragma unroll
    for (int mi = 0; mi < 4; mi++)
#pragma unroll
        for (int ni = 0; ni < 4; ni++)
#pragma unroll
            for (int r = 0; r < 4; r++) acc[mi][ni][r] = 0.0f;

    for (int c = 0; c < 8; c++) {        // k chunks of 32
        const int k0 = c * 32;
        // --- A: 128 rows x 32 fp32 -> bf16 hi/lo (1024 float4, 4/thread)
#pragma unroll
        for (int i = 0; i < 4; i++) {
            int idx = tid + i * 256;             // [0,1024)
            int row = idx >> 3;                  // [0,128)
            int c4  = idx & 7;                   // [0,8)
            float4 a = *(const float4*)&A[(size_t)(m0 + row) * DMODEL + k0 + c4 * 4];
            float hx = bf_round(a.x), hy = bf_round(a.y);
            float hz = bf_round(a.z), hw = bf_round(a.w);
            uint2 h = make_uint2(pack_bf2(a.x, a.y), pack_bf2(a.z, a.w));
            uint2 l = make_uint2(pack_bf2(a.x - hx, a.y - hy),
                                 pack_bf2(a.z - hz, a.w - hw));
            *(uint2*)&Ah[row * SROW + c4 * 4] = h;
            *(uint2*)&Al[row * SROW + c4 * 4] = l;
        }
        // --- B: pre-split bf16 [n][k]: 128 rows x 32 each for hi & lo (uint4)
#pragma unroll
        for (int i = 0; i < 4; i++) {
            int idx = tid + i * 256;             // [0,1024)
            int buf = idx >> 9;                  // 0=hi, 1=lo
            int row = (idx >> 2) & 127;
            int u   = idx & 3;                   // 16B unit
            const unsigned short* src = (buf == 0) ? WH : WL;
            uint4 w = *(const uint4*)&src[(size_t)(n0 + row) * DMODEL + k0 + u * 8];
            unsigned short* dst = (buf == 0) ? Bh : Bl;
            *(uint4*)&dst[row * SROW + u * 8] = w;
        }
        __syncthreads();

#pragma unroll
        for (int ks = 0; ks < 2; ks++) {
            const int kbb = ks * 32;             // byte offset of k16 step
            unsigned afh[4][4], afl[4][4];
#pragma unroll
            for (int mi = 0; mi < 4; mi++) {
                unsigned off = (unsigned)((warp_m + mi * 16 + aRow) * (SROW * 2) + kbb + aKb);
                ldmx4(afh[mi], ahB + off);
                ldmx4(afl[mi], alB + off);
            }
#pragma unroll
            for (int pair = 0; pair < 2; pair++) {
                unsigned bfh[4], bfl[4];
                unsigned off = (unsigned)((warp_n + pair * 16 + bRow) * (SROW * 2) + kbb + bKb);
                ldmx4(bfh, bhB + off);
                ldmx4(bfl, blB + off);
#pragma unroll
                for (int mi = 0; mi < 4; mi++) {
#pragma unroll
                    for (int nj = 0; nj < 2; nj++) {
                        int ni = pair * 2 + nj;
                        mma16816(acc[mi][ni], afh[mi], &bfh[nj * 2]);
                        mma16816(acc[mi][ni], afl[mi], &bfh[nj * 2]);
                        mma16816(acc[mi][ni], afh[mi], &bfl[nj * 2]);
                    }
                }
            }
        }
        __syncthreads();
    }

    // Epilogue: C-fragment thread t holds (row = t/4 [+8], col = 2*(t%4)+{0,1})
    const int qr = lane >> 2;
    const int qc = (lane & 3) * 2;
#pragma unroll
    for (int mi = 0; mi < 4; mi++) {
#pragma unroll
        for (int ni = 0; ni < 4; ni++) {
            int colg = n0 + warp_n + ni * 8 + qc;        // global col (even)
            float b0 = sbias[colg], b1 = sbias[colg + 1];
            int r0 = m0 + warp_m + mi * 16 + qr;
            int r1 = r0 + 8;
            float2 w0 = make_float2(acc[mi][ni][0] + b0, acc[mi][ni][1] + b1);
            float2 w1 = make_float2(acc[mi][ni][2] + b0, acc[mi][ni][3] + b1);
            if (MODE == 0) {
                *(float2*)&C[(size_t)r0 * DMODEL + colg] = w0;
                *(float2*)&C[(size_t)r1 * DMODEL + colg] = w1;
            } else {
                int hd = colg >> 5;
                int dh = colg & 31;
                int s0 = r0 >> 6, t0 = r0 & 63;
                int s1 = r1 >> 6, t1 = r1 & 63;
                *(float2*)&C[(((size_t)s0 * NHEADS + hd) * TLEN + t0) * DHEAD + dh] = w0;
                *(float2*)&C[(((size_t)s1 * NHEADS + hd) * TLEN + t1) * DHEAD + dh] = w1;
            }
        }
    }
}

__global__ void __launch_bounds__(256, 2)
qkv_mma_kernel(const float* __restrict__ q, const float* __restrict__ k,
               const float* __restrict__ v,
               const float* __restrict__ bq, const float* __restrict__ bk,
               const float* __restrict__ bv)
{
    int z = blockIdx.z;
    if (z == 0)      gemm_mma<1>(q, 0, bq, g_q);
    else if (z == 1) gemm_mma<1>(k, 1, bk, g_k);
    else             gemm_mma<1>(v, 2, bv, g_v);
}

__global__ void __launch_bounds__(256, 2)
out_mma_kernel(const float* __restrict__ bo, float* __restrict__ C)
{
    gemm_mma<0>(g_ctx, 3, bo, C);
}

// ---------------------------------------------------------------------------
// Attention: one CTA per (seq, head). (unchanged from passing R7 version)
// ---------------------------------------------------------------------------
__global__ void __launch_bounds__(256)
attn_kernel(const float* __restrict__ mask, float* __restrict__ attn_out)
{
    __shared__ float qs[64][33];
    __shared__ __align__(16) float kst[32][66];
    __shared__ __align__(16) float vs[64][32];
    __shared__ __align__(16) float ls[64][68];
    __shared__ float msk[64];

    const int head = blockIdx.x;           // seq*NH + n
    const int b    = head >> 11;           // batch index
    const int tid  = threadIdx.x;
    const float scale = 0.17677669529663687f;  // 1/sqrt(32)

    const float* qp = g_q + (size_t)head * (TLEN * DHEAD);
    const float* kp = g_k + (size_t)head * (TLEN * DHEAD);
    const float* vp = g_v + (size_t)head * (TLEN * DHEAD);

    if (tid < 64) msk[tid] = mask[b * 64 + tid] * (-1e9f);

#pragma unroll
    for (int i = 0; i < 2; i++) {
        int idx = tid + i * 256;
        int r = idx >> 3;
        int c = (idx & 7) * 4;
        float4 qv = ((const float4*)qp)[idx];
        qs[r][c + 0] = qv.x * scale; qs[r][c + 1] = qv.y * scale;
        qs[r][c + 2] = qv.z * scale; qs[r][c + 3] = qv.w * scale;
        float4 kv = ((const float4*)kp)[idx];
        kst[c + 0][r] = kv.x; kst[c + 1][r] = kv.y;
        kst[c + 2][r] = kv.z; kst[c + 3][r] = kv.w;
        *(float4*)&vs[r][c] = ((const float4*)vp)[idx];
    }
    __syncthreads();

    {
        const int r   = tid >> 2;
        const int cq  = tid & 3;
        const int c0  = cq * 16;

        float qr[32];
#pragma unroll
        for (int d = 0; d < 32; d++) qr[d] = qs[r][d];

        unsigned long long acc2[8];
#pragma unroll
        for (int p = 0; p < 8; p++) acc2[p] = 0ull;
#pragma unroll
        for (int d = 0; d < 32; d++) {
            unsigned long long aa = pack_dup(qr[d]);
            const unsigned long long* kp2 = (const unsigned long long*)&kst[d][c0];
#pragma unroll
            for (int p = 0; p < 8; p++) acc2[p] = fma2(aa, kp2[p], acc2[p]);
        }

        float lg[16];
#pragma unroll
        for (int p = 0; p < 8; p++) {
            float2 f = unpack2(acc2[p]);
            lg[2 * p + 0] = f.x + msk[c0 + 2 * p + 0];
            lg[2 * p + 1] = f.y + msk[c0 + 2 * p + 1];
        }

        float mx = lg[0];
#pragma unroll
        for (int i = 1; i < 16; i++) mx = fmaxf(mx, lg[i]);
        mx = fmaxf(mx, __shfl_xor_sync(0xffffffffu, mx, 1));
        mx = fmaxf(mx, __shfl_xor_sync(0xffffffffu, mx, 2));

        float sum = 0.0f;
#pragma unroll
        for (int i = 0; i < 16; i++) {
            float e = expf(lg[i] - mx);
            lg[i] = e;
            sum += e;
        }
        sum += __shfl_xor_sync(0xffffffffu, sum, 1);
        sum += __shfl_xor_sync(0xffffffffu, sum, 2);
        float inv = 1.0f / sum;

#pragma unroll
        for (int p = 0; p < 4; p++) {
            float4 w = make_float4(lg[4 * p + 0] * inv, lg[4 * p + 1] * inv,
                                   lg[4 * p + 2] * inv, lg[4 * p + 3] * inv);
            *(float4*)&ls[r][c0 + 4 * p] = w;
        }
    }
    __syncthreads();

    if (attn_out != nullptr) {
        float* ap = attn_out + (size_t)head * (TLEN * TLEN);
        for (int i = tid; i < TLEN * TLEN; i += 256)
            ap[i] = ls[i >> 6][i & 63];
    }

    {
        int r   = tid >> 2;
        int dh0 = (tid & 3) * 8;
        unsigned long long o2[4] = {0ull, 0ull, 0ull, 0ull};
#pragma unroll
        for (int s = 0; s < 64; s++) {
            unsigned long long aa = pack_dup(ls[r][s]);
            const unsigned long long* vp2 = (const unsigned long long*)&vs[s][dh0];
#pragma unroll
            for (int p = 0; p < 4; p++) o2[p] = fma2(aa, vp2[p], o2[p]);
        }
        float o[8];
#pragma unroll
        for (int p = 0; p < 4; p++) {
            float2 f = unpack2(o2[p]);
            o[2 * p + 0] = f.x;
            o[2 * p + 1] = f.y;
        }
        int seq = head >> 3;
        int n   = head & 7;
        size_t base = (((size_t)seq * TLEN + r) * DMODEL) + n * DHEAD + dh0;
        *(float4*)&g_ctx[base]     = make_float4(o[0], o[1], o[2], o[3]);
        *(float4*)&g_ctx[base + 4] = make_float4(o[4], o[5], o[6], o[7]);
    }
}

// ---------------------------------------------------------------------------
extern "C" void kernel_launch(void* const* d_in, const int* in_sizes, int n_in,
                              void* d_out, int out_size)
{
    const float* v    = (const float*)d_in[0];
    const float* k    = (const float*)d_in[1];
    const float* q    = (const float*)d_in[2];
    const float* mask = (const float*)d_in[3];
    const float* wq_w = (const float*)d_in[4];
    const float* wq_b = (const float*)d_in[5];
    const float* wk_w = (const float*)d_in[6];
    const float* wk_b = (const float*)d_in[7];
    const float* wv_w = (const float*)d_in[8];
    const float* wv_b = (const float*)d_in[9];
    const float* wo_w = (const float*)d_in[10];
    const float* wo_b = (const float*)d_in[11];

    float* outp  = nullptr;
    float* attnp = nullptr;
    long osz = (long)out_size;
    if (osz >= OUT_ELEMS + ATTN_ELEMS) {
        outp  = (float*)d_out;
        attnp = (float*)d_out + OUT_ELEMS;
    } else if (osz == ATTN_ELEMS) {
        attnp = (float*)d_out;
        outp  = nullptr;
    } else {
        outp  = (float*)d_out;
        attnp = nullptr;
    }

    // 0) Weight transpose + bf16 hi/lo split (tiny)
    prep_weights_kernel<<<4 * DMODEL * DMODEL / 256, 256>>>(wq_w, wk_w, wv_w, wo_w);

    // 1) QKV projections on mma.sync tensor cores -> head-split scratch
    dim3 g1(DMODEL / 128, TOKENS / 128, 3);
    qkv_mma_kernel<<<g1, 256>>>(q, k, v, wq_b, wk_b, wv_b);

    // 2) Attention per (seq, head)
    attn_kernel<<<SEQS * NHEADS, 256>>>(mask, attnp);

    // 3) Output projection on mma.sync tensor cores
    dim3 g2(DMODEL / 128, TOKENS / 128);
    out_mma_kernel<<<g2, 256>>>(wo_b, outp ? outp : g_q);
}

// round 13
// speedup vs baseline: 2.5939x; 1.6109x over previous
#include <cuda_runtime.h>
#include <cuda_bf16.h>
#include <math.h>

// Problem constants
#define DMODEL 256
#define TLEN   64
#define NHEADS 8
#define DHEAD  32
#define SEQS   1024                 // B*H*W
#define TOKENS (SEQS * TLEN)        // 65536
#define OUT_ELEMS  ((long)TOKENS * DMODEL)             // 16,777,216
#define ATTN_ELEMS ((long)SEQS * NHEADS * TLEN * TLEN) // 33,554,432
#define QSCALE 0.17677669529663687f                    // 1/sqrt(32)

// ---------------------------------------------------------------------------
// Device scratch (no allocation allowed)
// ---------------------------------------------------------------------------
// Head-split bf16 hi/lo q,k,v: [seq][n][t][dh] (ushort bf16 bits)
__device__ __align__(128) unsigned short g_qh[TOKENS * DMODEL];
__device__ __align__(128) unsigned short g_ql[TOKENS * DMODEL];
__device__ __align__(128) unsigned short g_kh[TOKENS * DMODEL];
__device__ __align__(128) unsigned short g_kl[TOKENS * DMODEL];
__device__ __align__(128) unsigned short g_vh[TOKENS * DMODEL];
__device__ __align__(128) unsigned short g_vl[TOKENS * DMODEL];
__device__ __align__(128) float g_ctx[TOKENS * DMODEL];  // merged heads [token][d]
// Pre-transposed, hi/lo-split weights: [g][n*256 + k]
__device__ __align__(128) unsigned short g_wt_hi[4][DMODEL * DMODEL];
__device__ __align__(128) unsigned short g_wt_lo[4][DMODEL * DMODEL];

// ---------------------------------------------------------------------------
// Helpers (all baseline sm_80/90 PTX)
// ---------------------------------------------------------------------------
__device__ __forceinline__ unsigned smem_u32(const void* p) {
    unsigned a;
    asm("{ .reg .u64 t; cvta.to.shared.u64 t, %1; cvt.u32.u64 %0, t; }"
        : "=r"(a) : "l"(p));
    return a;
}
// pack two fp32 -> bf16x2 (e0 -> low half)
__device__ __forceinline__ unsigned pack_bf2(float e0, float e1) {
    unsigned r;
    asm("cvt.rn.bf16x2.f32 %0, %1, %2;" : "=r"(r) : "f"(e1), "f"(e0));
    return r;
}
__device__ __forceinline__ float bf_round(float x) {
    return __bfloat162float(__float2bfloat16_rn(x));
}
__device__ __forceinline__ void ldmx4(unsigned* r, unsigned addr) {
    asm volatile("ldmatrix.sync.aligned.m8n8.x4.shared.b16 {%0,%1,%2,%3}, [%4];"
                 : "=r"(r[0]), "=r"(r[1]), "=r"(r[2]), "=r"(r[3]) : "r"(addr));
}
__device__ __forceinline__ void mma16816(float* d, const unsigned* a, const unsigned* b) {
    asm volatile(
        "mma.sync.aligned.m16n8k16.row.col.f32.bf16.bf16.f32 "
        "{%0,%1,%2,%3}, {%4,%5,%6,%7}, {%8,%9}, {%0,%1,%2,%3};"
        : "+f"(d[0]), "+f"(d[1]), "+f"(d[2]), "+f"(d[3])
        : "r"(a[0]), "r"(a[1]), "r"(a[2]), "r"(a[3]), "r"(b[0]), "r"(b[1]));
}
// split fp32 pair -> bf16 hi + lo pairs
__device__ __forceinline__ void split2(float x0, float x1, ushort2& h, ushort2& l) {
    __nv_bfloat16 h0 = __float2bfloat16_rn(x0);
    __nv_bfloat16 h1 = __float2bfloat16_rn(x1);
    h.x = __bfloat16_as_ushort(h0);
    h.y = __bfloat16_as_ushort(h1);
    l.x = __bfloat16_as_ushort(__float2bfloat16_rn(x0 - __bfloat162float(h0)));
    l.y = __bfloat16_as_ushort(__float2bfloat16_rn(x1 - __bfloat162float(h1)));
}

// ---------------------------------------------------------------------------
// Weight prep: W[k][n] fp32 -> Wt_hi/Wt_lo[n][k] bf16 (transposed + hi/lo split)
// q-scale folded into the wq weights (g==0).
// ---------------------------------------------------------------------------
__global__ void prep_weights_kernel(const float* __restrict__ wq,
                                    const float* __restrict__ wk,
                                    const float* __restrict__ wv,
                                    const float* __restrict__ wo)
{
    int i = blockIdx.x * 256 + threadIdx.x;      // 0 .. 4*65536-1
    int g = i >> 16;
    int r = i & 65535;
    int n = r >> 8;
    int k = r & 255;
    const float* W = (g == 0) ? wq : (g == 1) ? wk : (g == 2) ? wv : wo;
    float x = W[k * DMODEL + n];
    if (g == 0) x *= QSCALE;
    __nv_bfloat16 hb = __float2bfloat16_rn(x);
    float hf = __bfloat162float(hb);
    __nv_bfloat16 lb = __float2bfloat16_rn(x - hf);
    g_wt_hi[g][(n << 8) | k] = __bfloat16_as_ushort(hb);
    g_wt_lo[g][(n << 8) | k] = __bfloat16_as_ushort(lb);
}

// ---------------------------------------------------------------------------
// mma.sync bf16 GEMM with hi/lo split (validated R11 structure).
// MODE 0: fp32 row-major store to Cf.
// MODE 1: head-split bf16 hi/lo store to (Ch, Cl).
// ---------------------------------------------------------------------------
#define SROW 40

template <int MODE>
__device__ __forceinline__ void gemm_mma(const float* __restrict__ A, int g,
                                         const float* __restrict__ bias,
                                         float bscale,
                                         float* __restrict__ Cf,
                                         unsigned short* __restrict__ Ch,
                                         unsigned short* __restrict__ Cl)
{
    __shared__ __align__(16) unsigned short Ah[128 * SROW];
    __shared__ __align__(16) unsigned short Al[128 * SROW];
    __shared__ __align__(16) unsigned short Bh[128 * SROW];
    __shared__ __align__(16) unsigned short Bl[128 * SROW];
    __shared__ float sbias[DMODEL];

    const int tid  = threadIdx.x;
    const int lane = tid & 31;
    const int wid  = tid >> 5;
    const int m0   = blockIdx.y * 128;
    const int n0   = blockIdx.x * 128;
    const int warp_m = (wid >> 2) * 64;   // 0 or 64
    const int warp_n = (wid & 3) * 32;    // 0,32,64,96

    const unsigned short* __restrict__ WH = g_wt_hi[g];
    const unsigned short* __restrict__ WL = g_wt_lo[g];

    sbias[tid] = bias[tid] * bscale;

    const unsigned ahB = smem_u32(Ah);
    const unsigned alB = smem_u32(Al);
    const unsigned bhB = smem_u32(Bh);
    const unsigned blB = smem_u32(Bl);

    const int lg = lane >> 3;
    const int lr = lane & 7;
    const int aRow = lr + (lg & 1) * 8;
    const int aKb  = (lg >> 1) * 16;
    const int bRow = lr + (lg >> 1) * 8;
    const int bKb  = (lg & 1) * 16;

    float acc[4][4][4];
#pragma unroll
    for (int mi = 0; mi < 4; mi++)
#pragma unroll
        for (int ni = 0; ni < 4; ni++)
#pragma unroll
            for (int r = 0; r < 4; r++) acc[mi][ni][r] = 0.0f;

    for (int c = 0; c < 8; c++) {        // k chunks of 32
        const int k0 = c * 32;
#pragma unroll
        for (int i = 0; i < 4; i++) {
            int idx = tid + i * 256;
            int row = idx >> 3;
            int c4  = idx & 7;
            float4 a = *(const float4*)&A[(size_t)(m0 + row) * DMODEL + k0 + c4 * 4];
            float hx = bf_round(a.x), hy = bf_round(a.y);
            float hz = bf_round(a.z), hw = bf_round(a.w);
            uint2 h = make_uint2(pack_bf2(a.x, a.y), pack_bf2(a.z, a.w));
            uint2 l = make_uint2(pack_bf2(a.x - hx, a.y - hy),
                                 pack_bf2(a.z - hz, a.w - hw));
            *(uint2*)&Ah[row * SROW + c4 * 4] = h;
            *(uint2*)&Al[row * SROW + c4 * 4] = l;
        }
#pragma unroll
        for (int i = 0; i < 4; i++) {
            int idx = tid + i * 256;
            int buf = idx >> 9;
            int row = (idx >> 2) & 127;
            int u   = idx & 3;
            const unsigned short* src = (buf == 0) ? WH : WL;
            uint4 w = *(const uint4*)&src[(size_t)(n0 + row) * DMODEL + k0 + u * 8];
            unsigned short* dst = (buf == 0) ? Bh : Bl;
            *(uint4*)&dst[row * SROW + u * 8] = w;
        }
        __syncthreads();

#pragma unroll
        for (int ks = 0; ks < 2; ks++) {
            const int kbb = ks * 32;
            unsigned afh[4][4], afl[4][4];
#pragma unroll
            for (int mi = 0; mi < 4; mi++) {
                unsigned off = (unsigned)((warp_m + mi * 16 + aRow) * (SROW * 2) + kbb + aKb);
                ldmx4(afh[mi], ahB + off);
                ldmx4(afl[mi], alB + off);
            }
#pragma unroll
            for (int pair = 0; pair < 2; pair++) {
                unsigned bfh[4], bfl[4];
                unsigned off = (unsigned)((warp_n + pair * 16 + bRow) * (SROW * 2) + kbb + bKb);
                ldmx4(bfh, bhB + off);
                ldmx4(bfl, blB + off);
#pragma unroll
                for (int mi = 0; mi < 4; mi++) {
#pragma unroll
                    for (int nj = 0; nj < 2; nj++) {
                        int ni = pair * 2 + nj;
                        mma16816(acc[mi][ni], afh[mi], &bfh[nj * 2]);
                        mma16816(acc[mi][ni], afl[mi], &bfh[nj * 2]);
                        mma16816(acc[mi][ni], afh[mi], &bfl[nj * 2]);
                    }
                }
            }
        }
        __syncthreads();
    }

    const int qr = lane >> 2;
    const int qc = (lane & 3) * 2;
#pragma unroll
    for (int mi = 0; mi < 4; mi++) {
#pragma unroll
        for (int ni = 0; ni < 4; ni++) {
            int colg = n0 + warp_n + ni * 8 + qc;
            float b0 = sbias[colg], b1 = sbias[colg + 1];
            int r0 = m0 + warp_m + mi * 16 + qr;
            int r1 = r0 + 8;
            float x00 = acc[mi][ni][0] + b0, x01 = acc[mi][ni][1] + b1;
            float x10 = acc[mi][ni][2] + b0, x11 = acc[mi][ni][3] + b1;
            if (MODE == 0) {
                *(float2*)&Cf[(size_t)r0 * DMODEL + colg] = make_float2(x00, x01);
                *(float2*)&Cf[(size_t)r1 * DMODEL + colg] = make_float2(x10, x11);
            } else {
                int hd = colg >> 5;
                int dh = colg & 31;
                int s0 = r0 >> 6, t0 = r0 & 63;
                int s1 = r1 >> 6, t1 = r1 & 63;
                size_t b0i = (((size_t)s0 * NHEADS + hd) * TLEN + t0) * DHEAD + dh;
                size_t b1i = (((size_t)s1 * NHEADS + hd) * TLEN + t1) * DHEAD + dh;
                ushort2 h, l;
                split2(x00, x01, h, l);
                *(ushort2*)&Ch[b0i] = h;
                *(ushort2*)&Cl[b0i] = l;
                split2(x10, x11, h, l);
                *(ushort2*)&Ch[b1i] = h;
                *(ushort2*)&Cl[b1i] = l;
            }
        }
    }
}

__global__ void __launch_bounds__(256, 2)
qkv_mma_kernel(const float* __restrict__ q, const float* __restrict__ k,
               const float* __restrict__ v,
               const float* __restrict__ bq, const float* __restrict__ bk,
               const float* __restrict__ bv)
{
    int z = blockIdx.z;
    if (z == 0)      gemm_mma<1>(q, 0, bq, QSCALE, nullptr, g_qh, g_ql);
    else if (z == 1) gemm_mma<1>(k, 1, bk, 1.0f,  nullptr, g_kh, g_kl);
    else             gemm_mma<1>(v, 2, bv, 1.0f,  nullptr, g_vh, g_vl);
}

__global__ void __launch_bounds__(256, 2)
out_mma_kernel(const float* __restrict__ bo, float* __restrict__ C)
{
    gemm_mma<0>(g_ctx, 3, bo, 1.0f, C, nullptr, nullptr);
}

// ---------------------------------------------------------------------------
// Tensor-core attention: 1 head per CTA, 128 threads (4 warps of 16 q-rows).
// S = QhKh + QlKh + QhKl (fp32 acc); register softmax (quad shfl);
// P re-split hi/lo, packed C-frag -> A-frag; O = PhVh + PlVh + PhVl.
// V transposed in smem [dh][s], pitch 72 (9x16B, coprime 8).
// ---------------------------------------------------------------------------
#define VROW 72

__global__ void __launch_bounds__(128)
attn_mma_kernel(const float* __restrict__ mask, float* __restrict__ attn_out)
{
    __shared__ __align__(16) char sm[29952];
    unsigned short* Qh  = (unsigned short*)(sm);            // 64 x SROW
    unsigned short* Ql  = (unsigned short*)(sm + 5120);
    unsigned short* Kh  = (unsigned short*)(sm + 10240);
    unsigned short* Kl  = (unsigned short*)(sm + 15360);
    float*          ls  = (float*)(sm);                      // overlay (17408B <= 20480)
    unsigned short* Vth = (unsigned short*)(sm + 20480);     // 32 x VROW
    unsigned short* Vtl = (unsigned short*)(sm + 25088);
    float*          msk = (float*)(sm + 29696);              // 64 floats

    const int head = blockIdx.x;          // seq*NH + n
    const int tid  = threadIdx.x;
    const int lane = tid & 31;
    const int wid  = tid >> 5;
    const int b    = head >> 11;

    if (tid < 64) msk[tid] = mask[b * 64 + tid] * (-1e9f);

    const size_t hb = (size_t)head * (TLEN * DHEAD);

    // Load Q,K hi/lo: 256 uint4 per buffer, 2 per thread each
#pragma unroll
    for (int i = 0; i < 2; i++) {
        int idx = tid + i * 128;          // [0,256)
        int r = idx >> 2;
        int u = idx & 3;
        unsigned off = (unsigned)(r * (SROW * 2) + u * 16);
        *(uint4*)((char*)Qh + off) = ((const uint4*)(g_qh + hb))[idx];
        *(uint4*)((char*)Ql + off) = ((const uint4*)(g_ql + hb))[idx];
        *(uint4*)((char*)Kh + off) = ((const uint4*)(g_kh + hb))[idx];
        *(uint4*)((char*)Kl + off) = ((const uint4*)(g_kl + hb))[idx];
    }
    // Transpose V into [dh][s]
#pragma unroll
    for (int i = 0; i < 16; i++) {
        int idx = tid + i * 128;          // [0,2048)
        int s  = idx >> 5;
        int dh = idx & 31;
        Vth[dh * VROW + s] = g_vh[hb + idx];
        Vtl[dh * VROW + s] = g_vl[hb + idx];
    }
    __syncthreads();

    const unsigned qhB = smem_u32(Qh), qlB = smem_u32(Ql);
    const unsigned khB = smem_u32(Kh), klB = smem_u32(Kl);
    const unsigned vhB = smem_u32(Vth), vlB = smem_u32(Vtl);

    const int lg = lane >> 3;
    const int lr = lane & 7;
    const int aRow = lr + (lg & 1) * 8;
    const int aKb  = (lg >> 1) * 16;
    const int bRow = lr + (lg >> 1) * 8;
    const int bKb  = (lg & 1) * 16;

    // ---- S = Q @ K^T (hi/lo, fp32 acc). Warp covers rows [16*wid, +16), all 64 cols.
    float sacc[8][4];
#pragma unroll
    for (int nt = 0; nt < 8; nt++)
#pragma unroll
        for (int r = 0; r < 4; r++) sacc[nt][r] = 0.0f;

#pragma unroll
    for (int ks = 0; ks < 2; ks++) {
        const int kbb = ks * 32;
        unsigned ah[4], al[4];
        unsigned aoff = (unsigned)((wid * 16 + aRow) * (SROW * 2) + kbb + aKb);
        ldmx4(ah, qhB + aoff);
        ldmx4(al, qlB + aoff);
#pragma unroll
        for (int np = 0; np < 4; np++) {
            unsigned bh[4], bl[4];
            unsigned boff = (unsigned)((np * 16 + bRow) * (SROW * 2) + kbb + bKb);
            ldmx4(bh, khB + boff);
            ldmx4(bl, klB + boff);
#pragma unroll
            for (int nj = 0; nj < 2; nj++) {
                int nt = np * 2 + nj;
                mma16816(sacc[nt], ah, &bh[nj * 2]);
                mma16816(sacc[nt], al, &bh[nj * 2]);
                mma16816(sacc[nt], ah, &bl[nj * 2]);
            }
        }
    }
    __syncthreads();   // Q/K smem dead; ls overlay becomes writable

    // ---- mask + softmax (rows r0 = 16*wid + lane/4 and r0+8; quad lanes share rows)
    const int cb = (lane & 3) * 2;
    float m0 = -1e30f, m1 = -1e30f;
#pragma unroll
    for (int nt = 0; nt < 8; nt++) {
        float k0 = msk[nt * 8 + cb], k1 = msk[nt * 8 + cb + 1];
        sacc[nt][0] += k0; sacc[nt][1] += k1;
        sacc[nt][2] += k0; sacc[nt][3] += k1;
        m0 = fmaxf(m0, fmaxf(sacc[nt][0], sacc[nt][1]));
        m1 = fmaxf(m1, fmaxf(sacc[nt][2], sacc[nt][3]));
    }
    m0 = fmaxf(m0, __shfl_xor_sync(0xffffffffu, m0, 1));
    m0 = fmaxf(m0, __shfl_xor_sync(0xffffffffu, m0, 2));
    m1 = fmaxf(m1, __shfl_xor_sync(0xffffffffu, m1, 1));
    m1 = fmaxf(m1, __shfl_xor_sync(0xffffffffu, m1, 2));

    float s0 = 0.0f, s1 = 0.0f;
#pragma unroll
    for (int nt = 0; nt < 8; nt++) {
        sacc[nt][0] = expf(sacc[nt][0] - m0); s0 += sacc[nt][0];
        sacc[nt][1] = expf(sacc[nt][1] - m0); s0 += sacc[nt][1];
        sacc[nt][2] = expf(sacc[nt][2] - m1); s1 += sacc[nt][2];
        sacc[nt][3] = expf(sacc[nt][3] - m1); s1 += sacc[nt][3];
    }
    s0 += __shfl_xor_sync(0xffffffffu, s0, 1);
    s0 += __shfl_xor_sync(0xffffffffu, s0, 2);
    s1 += __shfl_xor_sync(0xffffffffu, s1, 1);
    s1 += __shfl_xor_sync(0xffffffffu, s1, 2);
    float inv0 = 1.0f / s0, inv1 = 1.0f / s1;
#pragma unroll
    for (int nt = 0; nt < 8; nt++) {
        sacc[nt][0] *= inv0; sacc[nt][1] *= inv0;
        sacc[nt][2] *= inv1; sacc[nt][3] *= inv1;
    }

    const int r0 = wid * 16 + (lane >> 2);
    // Stage P for the attn output (only if requested)
    if (attn_out != nullptr) {
#pragma unroll
        for (int nt = 0; nt < 8; nt++) {
            *(float2*)&ls[r0 * 68 + nt * 8 + cb]       = make_float2(sacc[nt][0], sacc[nt][1]);
            *(float2*)&ls[(r0 + 8) * 68 + nt * 8 + cb] = make_float2(sacc[nt][2], sacc[nt][3]);
        }
    }

    // ---- O = P @ V (hi/lo), P fragments packed from sacc
    float oacc[4][4];
#pragma unroll
    for (int nt = 0; nt < 4; nt++)
#pragma unroll
        for (int r = 0; r < 4; r++) oacc[nt][r] = 0.0f;

#pragma unroll
    for (int kt = 0; kt < 4; kt++) {
        float p00 = sacc[2 * kt][0],     p01 = sacc[2 * kt][1];
        float p02 = sacc[2 * kt][2],     p03 = sacc[2 * kt][3];
        float p10 = sacc[2 * kt + 1][0], p11 = sacc[2 * kt + 1][1];
        float p12 = sacc[2 * kt + 1][2], p13 = sacc[2 * kt + 1][3];
        unsigned ph[4], pl[4];
        ph[0] = pack_bf2(p00, p01); ph[1] = pack_bf2(p02, p03);
        ph[2] = pack_bf2(p10, p11); ph[3] = pack_bf2(p12, p13);
        pl[0] = pack_bf2(p00 - bf_round(p00), p01 - bf_round(p01));
        pl[1] = pack_bf2(p02 - bf_round(p02), p03 - bf_round(p03));
        pl[2] = pack_bf2(p10 - bf_round(p10), p11 - bf_round(p11));
        pl[3] = pack_bf2(p12 - bf_round(p12), p13 - bf_round(p13));
#pragma unroll
        for (int np = 0; np < 2; np++) {
            unsigned vh[4], vl[4];
            unsigned voff = (unsigned)((np * 16 + bRow) * (VROW * 2) + kt * 32 + bKb);
            ldmx4(vh, vhB + voff);
            ldmx4(vl, vlB + voff);
#pragma unroll
            for (int nj = 0; nj < 2; nj++) {
                int nt = np * 2 + nj;
                mma16816(oacc[nt], ph, &vh[nj * 2]);
                mma16816(oacc[nt], pl, &vh[nj * 2]);
                mma16816(oacc[nt], ph, &vl[nj * 2]);
            }
        }
    }

    // ---- write ctx (merged heads, fp32)
    {
        const int seq = head >> 3;
        const int hd  = head & 7;
#pragma unroll
        for (int nt = 0; nt < 4; nt++) {
            int dh = nt * 8 + cb;
            size_t base0 = ((size_t)(seq * TLEN + r0) * DMODEL) + hd * DHEAD + dh;
            size_t base1 = ((size_t)(seq * TLEN + r0 + 8) * DMODEL) + hd * DHEAD + dh;
            *(float2*)&g_ctx[base0] = make_float2(oacc[nt][0], oacc[nt][1]);
            *(float2*)&g_ctx[base1] = make_float2(oacc[nt][2], oacc[nt][3]);
        }
    }

    // ---- coalesced attn-probs write
    if (attn_out != nullptr) {
        __syncthreads();
        float* ap = attn_out + (size_t)head * (TLEN * TLEN);
#pragma unroll
        for (int i = 0; i < 32; i++) {
            int idx = tid + i * 128;      // [0,4096)
            ap[idx] = ls[(idx >> 6) * 68 + (idx & 63)];
        }
    }
}

// ---------------------------------------------------------------------------
extern "C" void kernel_launch(void* const* d_in, const int* in_sizes, int n_in,
                              void* d_out, int out_size)
{
    const float* v    = (const float*)d_in[0];
    const float* k    = (const float*)d_in[1];
    const float* q    = (const float*)d_in[2];
    const float* mask = (const float*)d_in[3];
    const float* wq_w = (const float*)d_in[4];
    const float* wq_b = (const float*)d_in[5];
    const float* wk_w = (const float*)d_in[6];
    const float* wk_b = (const float*)d_in[7];
    const float* wv_w = (const float*)d_in[8];
    const float* wv_b = (const float*)d_in[9];
    const float* wo_w = (const float*)d_in[10];
    const float* wo_b = (const float*)d_in[11];

    float* outp  = nullptr;
    float* attnp = nullptr;
    long osz = (long)out_size;
    if (osz >= OUT_ELEMS + ATTN_ELEMS) {
        outp  = (float*)d_out;
        attnp = (float*)d_out + OUT_ELEMS;
    } else if (osz == ATTN_ELEMS) {
        attnp = (float*)d_out;
        outp  = nullptr;
    } else {
        outp  = (float*)d_out;
        attnp = nullptr;
    }

    // 0) Weight transpose + bf16 hi/lo split (q-scale folded)
    prep_weights_kernel<<<4 * DMODEL * DMODEL / 256, 256>>>(wq_w, wk_w, wv_w, wo_w);

    // 1) QKV projections -> head-split bf16 hi/lo
    dim3 g1(DMODEL / 128, TOKENS / 128, 3);
    qkv_mma_kernel<<<g1, 256>>>(q, k, v, wq_b, wk_b, wv_b);

    // 2) Tensor-core attention, 1 head per CTA
    attn_mma_kernel<<<SEQS * NHEADS, 128>>>(mask, attnp);

    // 3) Output projection (skip entirely if out isn't requested)
    if (outp != nullptr) {
        dim3 g2(DMODEL / 128, TOKENS / 128);
        out_mma_kernel<<<g2, 256>>>(wo_b, outp);
    }
}